// round 9
// baseline (speedup 1.0000x reference)
#include <cuda_runtime.h>
#include <cuda_bf16.h>
#include <cstdint>

// ShortConv: causal depthwise Conv1d (K=4) + SiLU.
// x: (B=4, L=4096, D=2048) fp32, D contiguous. w: (D, 1, 4) fp32.
// y[b,l,d] = silu( sum_{k=0..3} w[d,0,k] * x[b, l-3+k, d] ), OOB x -> 0.
//
// R8 = R7 resubmit (R7 bench died at container acquisition; 3rd infra failure,
// never during kernel execution).
//
// R7 vs R6 (51.2us / ncu 42.0; DRAM 65.3%, issue 43%, alu 13.1% -> pipeline
// sync + LSU overhead co-binds with DRAM):
//  - Pair rows per cp.async group: one wait+commit per 2 rows (sync instr/byte
//    halved; adjacent LDGSTS batch at the LSU).
//  - Ring 5 pair-slots x 2 rows (40KB, x5 CTAs = 200KB fits): 8 rows in flight
//    (was 7).

#define DIM        2048
#define D4         (DIM / 4)       // 512 float4 per row
#define SEQLEN     4096
#define BATCH      4
#define THREADS    256
#define DGROUPS    (D4 / THREADS)  // 2
#define NCOLS      (BATCH * DGROUPS)          // 8
#define TOTAL_ROWS (NCOLS * SEQLEN)           // 32768
#define NCTAS      740                        // 148 SMs x occ 5
#define PSLOTS     5                          // pair slots in ring
#define ROW_BYTES  (THREADS * 16)             // 4KB per row stage

__device__ __forceinline__ void cp_async16(uint32_t dst_smem, const void* src) {
    asm volatile("cp.async.cg.shared.global [%0], [%1], 16;\n"
                 :: "r"(dst_smem), "l"(src));
}
__device__ __forceinline__ void cp_commit() {
    asm volatile("cp.async.commit_group;\n");
}
__device__ __forceinline__ void cp_wait3() {  // wait until <= 3 groups pending
    asm volatile("cp.async.wait_group 3;\n");
}

__device__ __forceinline__ float silu1(float v) {
    // silu(v) = 0.5*v*(1 + tanh(v/2)); tanh.approx = 1 MUFU.
    float t, h = 0.5f * v;
    asm("tanh.approx.f32 %0, %1;" : "=f"(t) : "f"(h));
    return fmaf(h, t, h);
}

__global__ __launch_bounds__(THREADS, 5)
void shortconv_silu_kernel(const float4* __restrict__ x,
                           const float4* __restrict__ w4,
                           float4* __restrict__ y) {
    __shared__ float4 ring[PSLOTS][2][THREADS];

    const uint32_t ring_base =
        (uint32_t)__cvta_generic_to_shared(&ring[0][0][threadIdx.x]);

    const unsigned int cta = blockIdx.x;
    unsigned int r0 = (unsigned int)(((unsigned long long)cta       * TOTAL_ROWS) / NCTAS);
    const unsigned int r1 = (unsigned int)(((unsigned long long)(cta + 1) * TOTAL_ROWS) / NCTAS);

    const float4 zero = make_float4(0.f, 0.f, 0.f, 0.f);

    while (r0 < r1) {
        const unsigned int c = r0 >> 12;            // column: b*DGROUPS + dg
        const unsigned int l = r0 & (SEQLEN - 1);   // row within column
        const unsigned int seg_end = min(r1, (c + 1) << 12);
        const int n = (int)(seg_end - r0);

        const int dg = c & (DGROUPS - 1);
        const int b  = c >> 1;
        const int d4 = dg * THREADS + threadIdx.x;

        // Channel taps: w floats are [d*4+k]; this lane's 4 channels = 4 contiguous float4.
        const float4 wa = w4[d4 * 4 + 0];
        const float4 wb = w4[d4 * 4 + 1];
        const float4 wc = w4[d4 * 4 + 2];
        const float4 wd = w4[d4 * 4 + 3];

        const float4* xp = x + ((size_t)b * SEQLEN + l) * D4 + d4;
        float4*       yp = y + ((size_t)b * SEQLEN + l) * D4 + d4;

        // Causal window preload (overlaps with pipeline prologue).
        float4 xm3 = (l >= 3) ? __ldcs(xp - 3 * D4) : zero;
        float4 xm2 = (l >= 2) ? __ldcs(xp - 2 * D4) : zero;
        float4 xm1 = (l >= 1) ? __ldcs(xp - 1 * D4) : zero;

        // Prologue: issue pairs 0..3 (rows 0..7, guarded), one group per pair.
        #pragma unroll
        for (int s = 0; s < PSLOTS - 1; ++s) {
            const int i0 = 2 * s, i1 = 2 * s + 1;
            if (i0 < n) cp_async16(ring_base + (2 * s + 0) * ROW_BYTES, xp + i0 * D4);
            if (i1 < n) cp_async16(ring_base + (2 * s + 1) * ROW_BYTES, xp + i1 * D4);
            cp_commit();
        }

        int slot  = 0;           // read slot  = p % 5
        int islot = PSLOTS - 1;  // issue slot = (p+4) % 5
        for (int p = 0; 2 * p < n; ++p) {
            cp_wait3();          // pair p landed
            const int i0 = 2 * p, i1 = i0 + 1;

            const float4 xc0 = ring[slot][0][threadIdx.x];
            const float4 xc1 = ring[slot][1][threadIdx.x];

            // Refill pair p+4 (rows i0+8, i0+9) into islot; commit (maybe empty).
            {
                const int j0 = i0 + 2 * (PSLOTS - 1), j1 = j0 + 1;
                const uint32_t ib = ring_base + (2 * islot) * ROW_BYTES;
                if (j0 < n) cp_async16(ib,             xp + j0 * D4);
                if (j1 < n) cp_async16(ib + ROW_BYTES, xp + j1 * D4);
                cp_commit();
            }

            // Row i0 (always valid: 2p < n).
            float4 r0v;
            r0v.x = fmaf(wa.x, xm3.x, fmaf(wa.y, xm2.x, fmaf(wa.z, xm1.x, wa.w * xc0.x)));
            r0v.y = fmaf(wb.x, xm3.y, fmaf(wb.y, xm2.y, fmaf(wb.z, xm1.y, wb.w * xc0.y)));
            r0v.z = fmaf(wc.x, xm3.z, fmaf(wc.y, xm2.z, fmaf(wc.z, xm1.z, wc.w * xc0.z)));
            r0v.w = fmaf(wd.x, xm3.w, fmaf(wd.y, xm2.w, fmaf(wd.z, xm1.w, wd.w * xc0.w)));
            r0v.x = silu1(r0v.x); r0v.y = silu1(r0v.y);
            r0v.z = silu1(r0v.z); r0v.w = silu1(r0v.w);
            __stcs(yp + i0 * D4, r0v);

            // Row i1 (guarded for odd tail).
            if (i1 < n) {
                float4 r1v;
                r1v.x = fmaf(wa.x, xm2.x, fmaf(wa.y, xm1.x, fmaf(wa.z, xc0.x, wa.w * xc1.x)));
                r1v.y = fmaf(wb.x, xm2.y, fmaf(wb.y, xm1.y, fmaf(wb.z, xc0.y, wb.w * xc1.y)));
                r1v.z = fmaf(wc.x, xm2.z, fmaf(wc.y, xm1.z, fmaf(wc.z, xc0.z, wc.w * xc1.z)));
                r1v.w = fmaf(wd.x, xm2.w, fmaf(wd.y, xm1.w, fmaf(wd.z, xc0.w, wd.w * xc1.w)));
                r1v.x = silu1(r1v.x); r1v.y = silu1(r1v.y);
                r1v.z = silu1(r1v.z); r1v.w = silu1(r1v.w);
                __stcs(yp + i1 * D4, r1v);
            }

            // Slide window by 2 rows.
            xm3 = xm1; xm2 = xc0; xm1 = xc1;

            slot  = (slot  + 1 == PSLOTS) ? 0 : slot  + 1;
            islot = (islot + 1 == PSLOTS) ? 0 : islot + 1;
        }

        r0 = seg_end;
    }
}

extern "C" void kernel_launch(void* const* d_in, const int* in_sizes, int n_in,
                              void* d_out, int out_size) {
    const float4* x  = (const float4*)d_in[0];
    const float4* w4 = (const float4*)d_in[1];
    float4*       y  = (float4*)d_out;

    shortconv_silu_kernel<<<NCTAS, THREADS>>>(x, w4, y);
}